// round 1
// baseline (speedup 1.0000x reference)
#include <cuda_runtime.h>
#include <cuda_bf16.h>
#include <math.h>

// Problem constants (fixed by the dataset)
#define Bn  4
#define Sn  8192
#define Dn  1024
#define SDn 512
#define Mn  (Bn * Sn)        // 32768 total rows
#define TS  64               // sequence tile for the scan
#define NT  (Sn / TS)        // 128 tiles per batch
#define RMS_EPS 1.1920929e-07f

// -------- scratch (static device globals; no runtime allocation) ----------
__device__ float g_z[Mn * SDn];          // 64 MB: z = sigmoid(g)*u, later h (pre-RMS)
__device__ float g_tilesum[Bn * NT * SDn]; // 1 MB: per-tile column sums -> exclusive prefix
__device__ float g_rmsinv[Mn];           // 128 KB: per-row rsqrt(mean(h^2)+eps)

// ===========================================================================
// K1: dual GEMM  g = x@Wg^T, u = x@Wu^T  (M=32768, N=512, K=1024)
//     z = sigmoid(g)*u  -> g_z ; per-64-row tile sums -> g_tilesum
// block: 256 threads, tile 64(m) x 64(n), K-chunk 16
// ===========================================================================
__global__ void k1_dualgemm(const float* __restrict__ x,
                            const float* __restrict__ Wu,
                            const float* __restrict__ Wg) {
    __shared__ float xs[16][68];   // [k][row], padded
    __shared__ float gs[16][68];   // [k][col] for W_gate
    __shared__ float us[16][68];   // [k][col] for W_update

    const int nt = blockIdx.x;         // 0..7   (SD tiles)
    const int mt = blockIdx.y;         // 0..511 (row tiles)
    const int m0 = mt * 64, n0 = nt * 64;
    const int tid = threadIdx.x;
    const int tx = tid & 15;           // col group (4 cols)
    const int ty = tid >> 4;           // row group (4 rows)

    float accg[4][4] = {}, accu[4][4] = {};

    const int lr = tid >> 2;           // loader row 0..63
    const int lc = (tid & 3) * 4;      // loader k-offset {0,4,8,12}

    const float* xp = x  + (size_t)(m0 + lr) * Dn + lc;
    const float* gp = Wg + (size_t)(n0 + lr) * Dn + lc;
    const float* up = Wu + (size_t)(n0 + lr) * Dn + lc;

    for (int k0 = 0; k0 < Dn; k0 += 16) {
        float4 vx = *(const float4*)(xp + k0);
        float4 vg = *(const float4*)(gp + k0);
        float4 vu = *(const float4*)(up + k0);
        __syncthreads();
        xs[lc+0][lr]=vx.x; xs[lc+1][lr]=vx.y; xs[lc+2][lr]=vx.z; xs[lc+3][lr]=vx.w;
        gs[lc+0][lr]=vg.x; gs[lc+1][lr]=vg.y; gs[lc+2][lr]=vg.z; gs[lc+3][lr]=vg.w;
        us[lc+0][lr]=vu.x; us[lc+1][lr]=vu.y; us[lc+2][lr]=vu.z; us[lc+3][lr]=vu.w;
        __syncthreads();
        #pragma unroll
        for (int kk = 0; kk < 16; kk++) {
            float a[4], bg[4], bu[4];
            *(float4*)a  = *(const float4*)&xs[kk][ty*4];
            *(float4*)bg = *(const float4*)&gs[kk][tx*4];
            *(float4*)bu = *(const float4*)&us[kk][tx*4];
            #pragma unroll
            for (int i = 0; i < 4; i++)
                #pragma unroll
                for (int j = 0; j < 4; j++) {
                    accg[i][j] = fmaf(a[i], bg[j], accg[i][j]);
                    accu[i][j] = fmaf(a[i], bu[j], accu[i][j]);
                }
        }
    }

    // epilogue: z = sigmoid(g)*u, write + partial column sums
    float psum[4] = {0.f, 0.f, 0.f, 0.f};
    #pragma unroll
    for (int i = 0; i < 4; i++) {
        const int row = m0 + ty*4 + i;
        #pragma unroll
        for (int j = 0; j < 4; j++) {
            float gsig = 1.0f / (1.0f + expf(-accg[i][j]));
            float zz = gsig * accu[i][j];
            g_z[(size_t)row * SDn + n0 + tx*4 + j] = zz;
            psum[j] += zz;
        }
    }
    __syncthreads();
    float* red = &xs[0][0];            // reuse smem: need 16*64 floats (have 16*68)
    #pragma unroll
    for (int j = 0; j < 4; j++) red[ty*64 + tx*4 + j] = psum[j];
    __syncthreads();
    if (tid < 64) {
        float s = 0.f;
        #pragma unroll
        for (int t = 0; t < 16; t++) s += red[t*64 + tid];
        const int b = mt / NT, tt = mt % NT;
        g_tilesum[(size_t)(b*NT + tt) * SDn + n0 + tid] = s;
    }
}

// ===========================================================================
// K2: exclusive prefix scan of tile sums over t, per (b, k) channel
// ===========================================================================
__global__ void k2_tileprefix() {
    int idx = blockIdx.x * blockDim.x + threadIdx.x;
    if (idx >= Bn * SDn) return;
    int b = idx / SDn, k = idx % SDn;
    float run = 0.f;
    for (int t = 0; t < NT; t++) {
        size_t off = (size_t)(b*NT + t) * SDn + k;
        float v = g_tilesum[off];
        g_tilesum[off] = run;
        run += v;
    }
}

// ===========================================================================
// K3a: per-tile scan along s, divide by running count, rewrite g_z in place,
//      compute per-row rms_inv. One block per 64-row tile, 512 threads (k).
// ===========================================================================
__global__ void k3a_scan_norm() {
    const int mt = blockIdx.x;            // 0..511
    const int b = mt / NT, t = mt % NT;
    const int k = threadIdx.x;            // 0..511
    const int warp = k >> 5, lane = k & 31;
    const int base = mt * 64;

    __shared__ float ssp[64][16];

    float carry = g_tilesum[(size_t)(b*NT + t) * SDn + k];

    #pragma unroll 4
    for (int r = 0; r < 64; r++) {
        const size_t off = (size_t)(base + r) * SDn + k;
        carry += g_z[off];
        float h = carry / (float)(t*64 + r + 1);
        g_z[off] = h;
        float sq = h * h;
        #pragma unroll
        for (int o = 16; o > 0; o >>= 1)
            sq += __shfl_xor_sync(0xffffffffu, sq, o);
        if (lane == 0) ssp[r][warp] = sq;
    }
    __syncthreads();
    if (k < 64) {
        float s = 0.f;
        #pragma unroll
        for (int w = 0; w < 16; w++) s += ssp[k][w];
        float ms = s * (1.0f / SDn);
        g_rmsinv[base + k] = rsqrtf(ms + RMS_EPS);
    }
}

// ===========================================================================
// K3b: out[m,d] = rms_inv[m] * sum_k h[m,k] * Wout[d,k]
//      M=32768, N=1024, K=512. Same tiling as K1, single accumulator set.
// ===========================================================================
__global__ void k3b_outgemm(const float* __restrict__ Wo,
                            float* __restrict__ out) {
    __shared__ float hs[16][68];
    __shared__ float ws[16][68];

    const int nt = blockIdx.x;         // 0..15 (D tiles)
    const int mt = blockIdx.y;         // 0..511
    const int m0 = mt * 64, n0 = nt * 64;
    const int tid = threadIdx.x;
    const int tx = tid & 15, ty = tid >> 4;

    float acc[4][4] = {};

    const int lr = tid >> 2;
    const int lc = (tid & 3) * 4;

    const float* hp = g_z + (size_t)(m0 + lr) * SDn + lc;
    const float* wp = Wo  + (size_t)(n0 + lr) * SDn + lc;

    for (int k0 = 0; k0 < SDn; k0 += 16) {
        float4 vh = *(const float4*)(hp + k0);
        float4 vw = *(const float4*)(wp + k0);
        __syncthreads();
        hs[lc+0][lr]=vh.x; hs[lc+1][lr]=vh.y; hs[lc+2][lr]=vh.z; hs[lc+3][lr]=vh.w;
        ws[lc+0][lr]=vw.x; ws[lc+1][lr]=vw.y; ws[lc+2][lr]=vw.z; ws[lc+3][lr]=vw.w;
        __syncthreads();
        #pragma unroll
        for (int kk = 0; kk < 16; kk++) {
            float a[4], bw[4];
            *(float4*)a  = *(const float4*)&hs[kk][ty*4];
            *(float4*)bw = *(const float4*)&ws[kk][tx*4];
            #pragma unroll
            for (int i = 0; i < 4; i++)
                #pragma unroll
                for (int j = 0; j < 4; j++)
                    acc[i][j] = fmaf(a[i], bw[j], acc[i][j]);
        }
    }

    #pragma unroll
    for (int i = 0; i < 4; i++) {
        const int row = m0 + ty*4 + i;
        const float rinv = g_rmsinv[row];
        float4 v;
        v.x = acc[i][0] * rinv;
        v.y = acc[i][1] * rinv;
        v.z = acc[i][2] * rinv;
        v.w = acc[i][3] * rinv;
        *(float4*)&out[(size_t)row * Dn + n0 + tx*4] = v;
    }
}

// ===========================================================================
extern "C" void kernel_launch(void* const* d_in, const int* in_sizes, int n_in,
                              void* d_out, int out_size) {
    const float* x  = (const float*)d_in[0];   // [4, 8192, 1024]
    const float* Wu = (const float*)d_in[1];   // [512, 1024]
    const float* Wg = (const float*)d_in[2];   // [512, 1024]
    const float* Wo = (const float*)d_in[3];   // [1024, 512]
    float* out = (float*)d_out;                // [4, 8192, 1024]

    k1_dualgemm<<<dim3(SDn/64, Mn/64), 256>>>(x, Wu, Wg);
    k2_tileprefix<<<(Bn*SDn + 255)/256, 256>>>();
    k3a_scan_norm<<<Mn/64, 512>>>();
    k3b_outgemm<<<dim3(Dn/64, Mn/64), 256>>>(Wo, out);
}

// round 3
// speedup vs baseline: 2.3848x; 2.3848x over previous
#include <cuda_runtime.h>
#include <cstdint>
#include <math.h>

// ---------------- problem constants ----------------
#define Bn  4
#define Sn  8192
#define Dn  1024
#define SDn 512
#define Mn  (Bn * Sn)          // 32768 rows
#define TS  128                // scan tile (rows) == BM
#define NT  (Sn / TS)          // 64 tiles per batch
#define RMS_EPS 1.1920929e-07f

// ---------------- GEMM tiling ----------------
#define BM 128
#define BN 128
#define BK 16
#define STAGES 3
#define SROW 20                              // padded floats per smem row
#define STAGE_FLOATS ((BM + BN) * SROW)      // 5120 floats
#define STAGE_BYTES  (STAGE_FLOATS * 4)      // 20480 B
#define SMEM_BYTES   (STAGES * STAGE_BYTES)  // 61440 B

// ---------------- scratch ----------------
__device__ __align__(128) float g_xt[Mn * Dn];        // x, tf32-rna
__device__ __align__(128) float g_wb[2 * SDn * Dn];   // interleaved Wg/Wu rows, tf32-rna
__device__ __align__(128) float g_wo[Dn * SDn];       // W_out tf32-rna
__device__ __align__(128) float g_z[Mn * SDn];        // z then h
__device__ __align__(128) float g_tilesum[(Mn / TS) * SDn];
__device__ __align__(128) float g_rmsinv[Mn];

// ---------------- helpers ----------------
__device__ __forceinline__ uint32_t smem_u32(const void* p) {
    uint32_t a;
    asm("{ .reg .u64 t; cvta.to.shared.u64 t, %1; cvt.u32.u64 %0, t; }" : "=r"(a) : "l"(p));
    return a;
}
__device__ __forceinline__ void cp16(uint32_t d, const float* s) {
    asm volatile("cp.async.cg.shared.global [%0], [%1], 16;" :: "r"(d), "l"(s));
}
#define CP_COMMIT() asm volatile("cp.async.commit_group;" ::: "memory")
#define CP_WAIT(n)  asm volatile("cp.async.wait_group %0;" :: "n"(n) : "memory")

__device__ __forceinline__ void mma_tf32(float* c, const uint32_t* a, uint32_t b0, uint32_t b1) {
    asm volatile(
        "mma.sync.aligned.m16n8k8.row.col.f32.tf32.tf32.f32 "
        "{%0,%1,%2,%3}, {%4,%5,%6,%7}, {%8,%9}, {%0,%1,%2,%3};"
        : "+f"(c[0]), "+f"(c[1]), "+f"(c[2]), "+f"(c[3])
        : "r"(a[0]), "r"(a[1]), "r"(a[2]), "r"(a[3]), "r"(b0), "r"(b1));
}
__device__ __forceinline__ float tf32_rna(float v) {
    uint32_t u;
    asm("cvt.rna.tf32.f32 %0, %1;" : "=r"(u) : "f"(v));
    return __uint_as_float(u);
}
__device__ __forceinline__ float sigmoidf_fast(float g) {
    return 1.0f / (1.0f + __expf(-g));
}

// ===========================================================================
// conversion kernels: fp32 -> tf32(RNA) bits
// ===========================================================================
__global__ void k_cvt(const float4* __restrict__ src, float4* __restrict__ dst, int n4) {
    for (int i = blockIdx.x * blockDim.x + threadIdx.x; i < n4; i += gridDim.x * blockDim.x) {
        float4 v = src[i];
        v.x = tf32_rna(v.x); v.y = tf32_rna(v.y);
        v.z = tf32_rna(v.z); v.w = tf32_rna(v.w);
        dst[i] = v;
    }
}
// interleave: dst row 2i <- Wg row i, dst row 2i+1 <- Wu row i (rows of Dn floats)
__global__ void k_cvt_pair(const float4* __restrict__ wg, const float4* __restrict__ wu,
                           float4* __restrict__ dst) {
    const int RW = Dn / 4;                       // 256 float4 per row
    const int total = SDn * RW;
    for (int i = blockIdx.x * blockDim.x + threadIdx.x; i < total; i += gridDim.x * blockDim.x) {
        int r = i / RW, c = i % RW;
        float4 vg = wg[i];
        vg.x = tf32_rna(vg.x); vg.y = tf32_rna(vg.y); vg.z = tf32_rna(vg.z); vg.w = tf32_rna(vg.w);
        dst[(size_t)(2 * r) * RW + c] = vg;
        float4 vu = wu[i];
        vu.x = tf32_rna(vu.x); vu.y = tf32_rna(vu.y); vu.z = tf32_rna(vu.z); vu.w = tf32_rna(vu.w);
        dst[(size_t)(2 * r + 1) * RW + c] = vu;
    }
}

// ===========================================================================
// shared GEMM mainloop (macro-free, inlined via functions)
// A: [M x K] row-major, B: [N x K] row-major (so C = A @ B^T), C tile 128x128
// 256 threads, warp grid 4(M) x 2(N), warp tile 32(M) x 64(N)
// ===========================================================================
struct Frag { float acc[2][8][4]; };

template<int KTOT>
__device__ __forceinline__ void gemm_mainloop(const float* __restrict__ A,
                                              const float* __restrict__ B,
                                              int m0, int n0, char* smem, Frag& f) {
    const int t = threadIdx.x;
    const int lr = t >> 1;            // loader row 0..127
    const int ls = t & 1;             // loader seg {0,1} -> segs ls, ls+2
    const uint32_t sb0 = smem_u32(smem);

    const float* Ag = A + (size_t)(m0 + lr) * KTOT + ls * 4;
    const float* Bg = B + (size_t)(n0 + lr) * KTOT + ls * 4;

    const int iters = KTOT / BK;

    // zero accumulators
    #pragma unroll
    for (int i = 0; i < 2; i++)
        #pragma unroll
        for (int j = 0; j < 8; j++)
            #pragma unroll
            for (int q = 0; q < 4; q++) f.acc[i][j][q] = 0.f;

    // prologue: fill STAGES-1 stages
    #pragma unroll
    for (int p = 0; p < STAGES - 1; p++) {
        uint32_t sa = sb0 + p * STAGE_BYTES + lr * (SROW * 4) + ls * 16;
        uint32_t sbB = sa + BM * (SROW * 4);
        cp16(sa,        Ag + p * BK);
        cp16(sa + 32,   Ag + p * BK + 8);
        cp16(sbB,       Bg + p * BK);
        cp16(sbB + 32,  Bg + p * BK + 8);
        CP_COMMIT();
    }

    const int wid = t >> 5, lane = t & 31;
    const int wm = wid & 3, wn = wid >> 2;
    const int gr = lane >> 2, gc = lane & 3;
    const int mrow = wm * 32, nb = wn * 64;

    int rs = 0;
    for (int it = 0; it < iters; it++) {
        CP_WAIT(STAGES - 2);
        __syncthreads();

        // issue loads for stage it+STAGES-1 into the stage we just freed
        if (it + STAGES - 1 < iters) {
            int ws = rs + STAGES - 1; if (ws >= STAGES) ws -= STAGES;
            int c = it + STAGES - 1;
            uint32_t sa = sb0 + ws * STAGE_BYTES + lr * (SROW * 4) + ls * 16;
            uint32_t sbB = sa + BM * (SROW * 4);
            cp16(sa,       Ag + c * BK);
            cp16(sa + 32,  Ag + c * BK + 8);
            cp16(sbB,      Bg + c * BK);
            cp16(sbB + 32, Bg + c * BK + 8);
        }
        CP_COMMIT();

        const float* As = (const float*)(smem + rs * STAGE_BYTES);
        const float* Bs = As + BM * SROW;

        #pragma unroll
        for (int kk = 0; kk < BK; kk += 8) {
            uint32_t a[2][4];
            #pragma unroll
            for (int mt = 0; mt < 2; mt++) {
                const int r = mrow + mt * 16 + gr;
                a[mt][0] = __float_as_uint(As[(r    ) * SROW + kk + gc]);
                a[mt][1] = __float_as_uint(As[(r + 8) * SROW + kk + gc]);
                a[mt][2] = __float_as_uint(As[(r    ) * SROW + kk + gc + 4]);
                a[mt][3] = __float_as_uint(As[(r + 8) * SROW + kk + gc + 4]);
            }
            #pragma unroll
            for (int nt = 0; nt < 8; nt++) {
                const int n = nb + nt * 8 + gr;
                uint32_t b0 = __float_as_uint(Bs[n * SROW + kk + gc]);
                uint32_t b1 = __float_as_uint(Bs[n * SROW + kk + gc + 4]);
                mma_tf32(f.acc[0][nt], a[0], b0, b1);
                mma_tf32(f.acc[1][nt], a[1], b0, b1);
            }
        }
        rs++; if (rs == STAGES) rs = 0;
    }
    CP_WAIT(0);
    __syncthreads();   // all warps done with smem before epilogue reuse
}

// ===========================================================================
// k1: C = x @ Wb^T (stacked interleaved weights, N=1024). Epilogue computes
// z = sigmoid(gate)*update in-register, writes g_z, and per-CTA tile column
// sums (CTA = one 128-row scan tile x 64 z-cols).
// ===========================================================================
__global__ void __launch_bounds__(256) k1_gemm() {
    extern __shared__ char smem[];
    const int n0 = blockIdx.x * BN;        // stacked col base (0..896)
    const int m0 = blockIdx.y * BM;
    Frag f;
    gemm_mainloop<Dn>(g_xt, g_wb, m0, n0, smem, f);

    const int t = threadIdx.x;
    const int wid = t >> 5, lane = t & 31;
    const int wm = wid & 3, wn = wid >> 2;
    const int gr = lane >> 2, gc = lane & 3;
    const int zbase = n0 >> 1;             // z col base (64 cols per CTA)

    float* csum = (float*)smem;            // 64 floats
    if (t < 64) csum[t] = 0.f;
    __syncthreads();

    #pragma unroll
    for (int mt = 0; mt < 2; mt++) {
        const int r0 = m0 + wm * 32 + mt * 16 + gr;
        #pragma unroll
        for (int nt = 0; nt < 8; nt++) {
            const int zc = zbase + wn * 32 + nt * 4 + gc;
            float z0 = f.acc[mt][nt][1] * sigmoidf_fast(f.acc[mt][nt][0]);
            float z1 = f.acc[mt][nt][3] * sigmoidf_fast(f.acc[mt][nt][2]);
            g_z[(size_t)r0 * SDn + zc] = z0;
            g_z[(size_t)(r0 + 8) * SDn + zc] = z1;
            atomicAdd(&csum[zc - zbase], z0 + z1);
        }
    }
    __syncthreads();
    if (t < 64)
        g_tilesum[(size_t)blockIdx.y * SDn + zbase + t] = csum[t];
}

// ===========================================================================
// k2: exclusive prefix over tiles per (b,k) channel
// ===========================================================================
__global__ void k2_tileprefix() {
    int idx = blockIdx.x * blockDim.x + threadIdx.x;   // 0..2047
    int b = idx / SDn, k = idx % SDn;
    float run = 0.f;
    for (int t = 0; t < NT; t++) {
        size_t off = (size_t)(b * NT + t) * SDn + k;
        float v = g_tilesum[off];
        g_tilesum[off] = run;
        run += v;
    }
}

// ===========================================================================
// k3a: in-tile scan + /denom, rewrite g_z with tf32-rna(h), per-row rms_inv
// ===========================================================================
__global__ void __launch_bounds__(512) k3a_scan() {
    const int mt = blockIdx.x;             // 0..255
    const int t = mt & (NT - 1);
    const int k = threadIdx.x;             // 0..511
    const int warp = k >> 5, lane = k & 31;
    const int base = mt * TS;

    __shared__ float ssp[TS][16];

    float carry = g_tilesum[(size_t)mt * SDn + k];

    #pragma unroll 4
    for (int r = 0; r < TS; r++) {
        const size_t off = (size_t)(base + r) * SDn + k;
        carry += g_z[off];
        float h = __fdividef(carry, (float)(t * TS + r + 1));
        h = tf32_rna(h);
        g_z[off] = h;
        float sq = h * h;
        #pragma unroll
        for (int o = 16; o > 0; o >>= 1) sq += __shfl_xor_sync(0xffffffffu, sq, o);
        if (lane == 0) ssp[r][warp] = sq;
    }
    __syncthreads();
    if (k < TS) {
        float s = 0.f;
        #pragma unroll
        for (int w = 0; w < 16; w++) s += ssp[k][w];
        g_rmsinv[base + k] = rsqrtf(s * (1.0f / SDn) + RMS_EPS);
    }
}

// ===========================================================================
// k3b: out = rms_inv[m] * (h @ Wo^T), M=32768, N=1024, K=512
// ===========================================================================
__global__ void __launch_bounds__(256) k3b_gemm(float* __restrict__ out) {
    extern __shared__ char smem[];
    const int n0 = blockIdx.x * BN;
    const int m0 = blockIdx.y * BM;
    Frag f;
    gemm_mainloop<SDn>(g_z, g_wo, m0, n0, smem, f);

    const int t = threadIdx.x;
    const int wid = t >> 5, lane = t & 31;
    const int wm = wid & 3, wn = wid >> 2;
    const int gr = lane >> 2, gc = lane & 3;

    #pragma unroll
    for (int mt = 0; mt < 2; mt++) {
        const int r0 = m0 + wm * 32 + mt * 16 + gr;
        const float ri0 = g_rmsinv[r0];
        const float ri1 = g_rmsinv[r0 + 8];
        #pragma unroll
        for (int nt = 0; nt < 8; nt++) {
            const int col = n0 + wn * 64 + nt * 8 + gc * 2;
            float2 v0 = { f.acc[mt][nt][0] * ri0, f.acc[mt][nt][1] * ri0 };
            float2 v1 = { f.acc[mt][nt][2] * ri1, f.acc[mt][nt][3] * ri1 };
            *(float2*)&out[(size_t)r0 * Dn + col] = v0;
            *(float2*)&out[(size_t)(r0 + 8) * Dn + col] = v1;
        }
    }
}

// ===========================================================================
// host side
// ===========================================================================
extern "C" void kernel_launch(void* const* d_in, const int* in_sizes, int n_in,
                              void* d_out, int out_size) {
    const float* x  = (const float*)d_in[0];   // [4, 8192, 1024]
    const float* Wu = (const float*)d_in[1];   // [512, 1024]
    const float* Wg = (const float*)d_in[2];   // [512, 1024]
    const float* Wo = (const float*)d_in[3];   // [1024, 512]
    float* out = (float*)d_out;

    void *pxt, *pwb, *pwo;
    cudaGetSymbolAddress(&pxt, g_xt);
    cudaGetSymbolAddress(&pwb, g_wb);
    cudaGetSymbolAddress(&pwo, g_wo);

    cudaFuncSetAttribute(k1_gemm,  cudaFuncAttributeMaxDynamicSharedMemorySize, SMEM_BYTES);
    cudaFuncSetAttribute(k3b_gemm, cudaFuncAttributeMaxDynamicSharedMemorySize, SMEM_BYTES);

    // round inputs to tf32-rna (weights also interleaved for k1)
    k_cvt<<<4096, 256>>>((const float4*)x, (float4*)pxt, Mn * Dn / 4);
    k_cvt_pair<<<512, 256>>>((const float4*)Wg, (const float4*)Wu, (float4*)pwb);
    k_cvt<<<512, 256>>>((const float4*)Wo, (float4*)pwo, Dn * SDn / 4);

    k1_gemm<<<dim3(2 * SDn / BN, Mn / BM), 256, SMEM_BYTES>>>();
    k2_tileprefix<<<(Bn * SDn) / 256, 256>>>();
    k3a_scan<<<Mn / TS, 512>>>();
    k3b_gemm<<<dim3(Dn / BN, Mn / BM), 256, SMEM_BYTES>>>(out);
}

// round 4
// speedup vs baseline: 2.8210x; 1.1829x over previous
#include <cuda_runtime.h>
#include <cstdint>
#include <math.h>

// ---------------- problem constants ----------------
#define Bn  4
#define Sn  8192
#define Dn  1024
#define SDn 512
#define Mn  (Bn * Sn)          // 32768 rows
#define TS  128                // scan tile (rows) == BM
#define NT  (Sn / TS)          // 64 tiles per batch
#define RMS_EPS 1.1920929e-07f

// ---------------- GEMM tiling ----------------
#define BM 128
#define BN 128
#define BK 16
#define STAGES 3
#define SROW 20                              // padded floats per smem row
#define STAGE_FLOATS ((BM + BN) * SROW)      // 5120 floats
#define STAGE_BYTES  (STAGE_FLOATS * 4)      // 20480 B
#define SMEM_BYTES   (STAGES * STAGE_BYTES)  // 61440 B

// ---------------- scratch ----------------
__device__ __align__(128) float g_xt[Mn * Dn];        // x, tf32-rna
__device__ __align__(128) float g_wb[2 * SDn * Dn];   // interleaved Wg/Wu rows, tf32-rna
__device__ __align__(128) float g_wo[Dn * SDn];       // W_out tf32-rna
__device__ __align__(128) float g_z[Mn * SDn];        // z then h
__device__ __align__(128) float g_tilesum[(Mn / TS) * SDn];
__device__ __align__(128) float g_rmsinv[Mn];

// ---------------- helpers ----------------
__device__ __forceinline__ uint32_t smem_u32(const void* p) {
    uint32_t a;
    asm("{ .reg .u64 t; cvta.to.shared.u64 t, %1; cvt.u32.u64 %0, t; }" : "=r"(a) : "l"(p));
    return a;
}
__device__ __forceinline__ void cp16(uint32_t d, const float* s) {
    asm volatile("cp.async.cg.shared.global [%0], [%1], 16;" :: "r"(d), "l"(s));
}
#define CP_COMMIT() asm volatile("cp.async.commit_group;" ::: "memory")
#define CP_WAIT(n)  asm volatile("cp.async.wait_group %0;" :: "n"(n) : "memory")

__device__ __forceinline__ void mma_tf32(float* c, const uint32_t* a, uint32_t b0, uint32_t b1) {
    asm volatile(
        "mma.sync.aligned.m16n8k8.row.col.f32.tf32.tf32.f32 "
        "{%0,%1,%2,%3}, {%4,%5,%6,%7}, {%8,%9}, {%0,%1,%2,%3};"
        : "+f"(c[0]), "+f"(c[1]), "+f"(c[2]), "+f"(c[3])
        : "r"(a[0]), "r"(a[1]), "r"(a[2]), "r"(a[3]), "r"(b0), "r"(b1));
}
__device__ __forceinline__ void ldsm4(uint32_t& r0, uint32_t& r1, uint32_t& r2, uint32_t& r3,
                                      uint32_t addr) {
    asm volatile("ldmatrix.sync.aligned.m8n8.x4.shared.b16 {%0,%1,%2,%3}, [%4];"
        : "=r"(r0), "=r"(r1), "=r"(r2), "=r"(r3) : "r"(addr));
}
__device__ __forceinline__ float tf32_rna(float v) {
    uint32_t u;
    asm("cvt.rna.tf32.f32 %0, %1;" : "=r"(u) : "f"(v));
    return __uint_as_float(u);
}
__device__ __forceinline__ float sigmoidf_fast(float g) {
    return 1.0f / (1.0f + __expf(-g));
}

// ===========================================================================
// conversion kernels: fp32 -> tf32(RNA) bits
// ===========================================================================
__global__ void k_cvt(const float4* __restrict__ src, float4* __restrict__ dst, int n4) {
    for (int i = blockIdx.x * blockDim.x + threadIdx.x; i < n4; i += gridDim.x * blockDim.x) {
        float4 v = src[i];
        v.x = tf32_rna(v.x); v.y = tf32_rna(v.y);
        v.z = tf32_rna(v.z); v.w = tf32_rna(v.w);
        dst[i] = v;
    }
}
// interleave: dst row 2i <- Wg row i, dst row 2i+1 <- Wu row i (rows of Dn floats)
__global__ void k_cvt_pair(const float4* __restrict__ wg, const float4* __restrict__ wu,
                           float4* __restrict__ dst) {
    const int RW = Dn / 4;
    const int total = SDn * RW;
    for (int i = blockIdx.x * blockDim.x + threadIdx.x; i < total; i += gridDim.x * blockDim.x) {
        int r = i / RW, c = i % RW;
        float4 vg = wg[i];
        vg.x = tf32_rna(vg.x); vg.y = tf32_rna(vg.y); vg.z = tf32_rna(vg.z); vg.w = tf32_rna(vg.w);
        dst[(size_t)(2 * r) * RW + c] = vg;
        float4 vu = wu[i];
        vu.x = tf32_rna(vu.x); vu.y = tf32_rna(vu.y); vu.z = tf32_rna(vu.z); vu.w = tf32_rna(vu.w);
        dst[(size_t)(2 * r + 1) * RW + c] = vu;
    }
}

// ===========================================================================
// shared GEMM mainloop. A: [M x K] rm, B: [N x K] rm (C = A @ B^T), tile 128x128
// 256 threads, warp grid 4(M) x 2(N), warp tile 32(M) x 64(N)
// Fragment loads via ldmatrix.x4 (6 LDSM vs 24 LDS.32 per k8-step)
// ===========================================================================
struct Frag { float acc[2][8][4]; };

template<int KTOT>
__device__ __forceinline__ void gemm_mainloop(const float* __restrict__ A,
                                              const float* __restrict__ B,
                                              int m0, int n0, char* smem, Frag& f) {
    const int t = threadIdx.x;
    const int lr = t >> 1;            // loader row 0..127
    const int ls = t & 1;
    const uint32_t sb0 = smem_u32(smem);

    const float* Ag = A + (size_t)(m0 + lr) * KTOT + ls * 4;
    const float* Bg = B + (size_t)(n0 + lr) * KTOT + ls * 4;

    const int iters = KTOT / BK;

    #pragma unroll
    for (int i = 0; i < 2; i++)
        #pragma unroll
        for (int j = 0; j < 8; j++)
            #pragma unroll
            for (int q = 0; q < 4; q++) f.acc[i][j][q] = 0.f;

    #pragma unroll
    for (int p = 0; p < STAGES - 1; p++) {
        uint32_t sa = sb0 + p * STAGE_BYTES + lr * (SROW * 4) + ls * 16;
        uint32_t sbB = sa + BM * (SROW * 4);
        cp16(sa,        Ag + p * BK);
        cp16(sa + 32,   Ag + p * BK + 8);
        cp16(sbB,       Bg + p * BK);
        cp16(sbB + 32,  Bg + p * BK + 8);
        CP_COMMIT();
    }

    const int wid = t >> 5, lane = t & 31;
    const int wm = wid & 3, wn = wid >> 2;
    const int mrow = wm * 32, nb = wn * 64;

    // ldmatrix per-lane byte offsets (within a stage)
    // A x4: matrices [r0-7,k0-3],[r8-15,k0-3],[r0-7,k4-7],[r8-15,k4-7]
    const uint32_t arow = ((lane >> 3) & 1) * 8 + (lane & 7);
    const uint32_t acol = ((lane >> 4) & 1) * 4;
    const uint32_t a_off = ((mrow + arow) * SROW + acol) * 4;
    // B x4: matrices [n0-7,k0-3],[n0-7,k4-7],[n8-15,k0-3],[n8-15,k4-7]
    const uint32_t brow = ((lane >> 4) & 1) * 8 + (lane & 7);
    const uint32_t bcol = ((lane >> 3) & 1) * 4;
    const uint32_t b_off = (BM * SROW + (nb + brow) * SROW + bcol) * 4;

    int rs = 0;
    for (int it = 0; it < iters; it++) {
        CP_WAIT(STAGES - 2);
        __syncthreads();

        if (it + STAGES - 1 < iters) {
            int ws = rs + STAGES - 1; if (ws >= STAGES) ws -= STAGES;
            int c = it + STAGES - 1;
            uint32_t sa = sb0 + ws * STAGE_BYTES + lr * (SROW * 4) + ls * 16;
            uint32_t sbB = sa + BM * (SROW * 4);
            cp16(sa,       Ag + c * BK);
            cp16(sa + 32,  Ag + c * BK + 8);
            cp16(sbB,      Bg + c * BK);
            cp16(sbB + 32, Bg + c * BK + 8);
        }
        CP_COMMIT();

        const uint32_t sbase = sb0 + rs * STAGE_BYTES;

        #pragma unroll
        for (int kk = 0; kk < BK; kk += 8) {
            uint32_t a[2][4];
            ldsm4(a[0][0], a[0][1], a[0][2], a[0][3], sbase + a_off + kk * 4);
            ldsm4(a[1][0], a[1][1], a[1][2], a[1][3], sbase + a_off + 16 * SROW * 4 + kk * 4);
            uint32_t b[8][2];
            #pragma unroll
            for (int p = 0; p < 4; p++)
                ldsm4(b[2*p][0], b[2*p][1], b[2*p+1][0], b[2*p+1][1],
                      sbase + b_off + p * 16 * SROW * 4 + kk * 4);
            #pragma unroll
            for (int nt = 0; nt < 8; nt++) {
                mma_tf32(f.acc[0][nt], a[0], b[nt][0], b[nt][1]);
                mma_tf32(f.acc[1][nt], a[1], b[nt][0], b[nt][1]);
            }
        }
        rs++; if (rs == STAGES) rs = 0;
    }
    CP_WAIT(0);
    __syncthreads();
}

// ===========================================================================
// k1: C = x @ Wb^T (interleaved weights, N=1024). Epilogue: z = sigmoid(g)*u,
// write g_z, per-CTA 128-row tile column sums.
// ===========================================================================
__global__ void __launch_bounds__(256, 2) k1_gemm() {
    extern __shared__ char smem[];
    const int n0 = blockIdx.x * BN;
    const int m0 = blockIdx.y * BM;
    Frag f;
    gemm_mainloop<Dn>(g_xt, g_wb, m0, n0, smem, f);

    const int t = threadIdx.x;
    const int wid = t >> 5, lane = t & 31;
    const int wm = wid & 3, wn = wid >> 2;
    const int gr = lane >> 2, gc = lane & 3;
    const int zbase = n0 >> 1;

    float* csum = (float*)smem;
    if (t < 64) csum[t] = 0.f;
    __syncthreads();

    #pragma unroll
    for (int mt = 0; mt < 2; mt++) {
        const int r0 = m0 + wm * 32 + mt * 16 + gr;
        #pragma unroll
        for (int nt = 0; nt < 8; nt++) {
            const int zc = zbase + wn * 32 + nt * 4 + gc;
            float z0 = f.acc[mt][nt][1] * sigmoidf_fast(f.acc[mt][nt][0]);
            float z1 = f.acc[mt][nt][3] * sigmoidf_fast(f.acc[mt][nt][2]);
            g_z[(size_t)r0 * SDn + zc] = z0;
            g_z[(size_t)(r0 + 8) * SDn + zc] = z1;
            atomicAdd(&csum[zc - zbase], z0 + z1);
        }
    }
    __syncthreads();
    if (t < 64)
        g_tilesum[(size_t)blockIdx.y * SDn + zbase + t] = csum[t];
}

// ===========================================================================
// k2: exclusive prefix over tiles per (b,k) channel
// ===========================================================================
__global__ void k2_tileprefix() {
    int idx = blockIdx.x * blockDim.x + threadIdx.x;
    int b = idx / SDn, k = idx % SDn;
    float run = 0.f;
    for (int t = 0; t < NT; t++) {
        size_t off = (size_t)(b * NT + t) * SDn + k;
        float v = g_tilesum[off];
        g_tilesum[off] = run;
        run += v;
    }
}

// ===========================================================================
// k3a: in-tile scan + /denom, rewrite g_z with tf32-rna(h), per-row rms_inv
// ===========================================================================
__global__ void __launch_bounds__(512) k3a_scan() {
    const int mt = blockIdx.x;
    const int t = mt & (NT - 1);
    const int k = threadIdx.x;
    const int warp = k >> 5, lane = k & 31;
    const int base = mt * TS;

    __shared__ float ssp[TS][16];

    float carry = g_tilesum[(size_t)mt * SDn + k];

    #pragma unroll 4
    for (int r = 0; r < TS; r++) {
        const size_t off = (size_t)(base + r) * SDn + k;
        carry += g_z[off];
        float h = __fdividef(carry, (float)(t * TS + r + 1));
        h = tf32_rna(h);
        g_z[off] = h;
        float sq = h * h;
        #pragma unroll
        for (int o = 16; o > 0; o >>= 1) sq += __shfl_xor_sync(0xffffffffu, sq, o);
        if (lane == 0) ssp[r][warp] = sq;
    }
    __syncthreads();
    if (k < TS) {
        float s = 0.f;
        #pragma unroll
        for (int w = 0; w < 16; w++) s += ssp[k][w];
        g_rmsinv[base + k] = rsqrtf(s * (1.0f / SDn) + RMS_EPS);
    }
}

// ===========================================================================
// k3b: out = rms_inv[m] * (h @ Wo^T), M=32768, N=1024, K=512
// ===========================================================================
__global__ void __launch_bounds__(256, 2) k3b_gemm(float* __restrict__ out) {
    extern __shared__ char smem[];
    const int n0 = blockIdx.x * BN;
    const int m0 = blockIdx.y * BM;
    Frag f;
    gemm_mainloop<SDn>(g_z, g_wo, m0, n0, smem, f);

    const int t = threadIdx.x;
    const int wid = t >> 5, lane = t & 31;
    const int wm = wid & 3, wn = wid >> 2;
    const int gr = lane >> 2, gc = lane & 3;

    #pragma unroll
    for (int mt = 0; mt < 2; mt++) {
        const int r0 = m0 + wm * 32 + mt * 16 + gr;
        const float ri0 = g_rmsinv[r0];
        const float ri1 = g_rmsinv[r0 + 8];
        #pragma unroll
        for (int nt = 0; nt < 8; nt++) {
            const int col = n0 + wn * 64 + nt * 8 + gc * 2;
            float2 v0 = { f.acc[mt][nt][0] * ri0, f.acc[mt][nt][1] * ri0 };
            float2 v1 = { f.acc[mt][nt][2] * ri1, f.acc[mt][nt][3] * ri1 };
            *(float2*)&out[(size_t)r0 * Dn + col] = v0;
            *(float2*)&out[(size_t)(r0 + 8) * Dn + col] = v1;
        }
    }
}

// ===========================================================================
// host side
// ===========================================================================
extern "C" void kernel_launch(void* const* d_in, const int* in_sizes, int n_in,
                              void* d_out, int out_size) {
    const float* x  = (const float*)d_in[0];
    const float* Wu = (const float*)d_in[1];
    const float* Wg = (const float*)d_in[2];
    const float* Wo = (const float*)d_in[3];
    float* out = (float*)d_out;

    void *pxt, *pwb, *pwo;
    cudaGetSymbolAddress(&pxt, g_xt);
    cudaGetSymbolAddress(&pwb, g_wb);
    cudaGetSymbolAddress(&pwo, g_wo);

    cudaFuncSetAttribute(k1_gemm,  cudaFuncAttributeMaxDynamicSharedMemorySize, SMEM_BYTES);
    cudaFuncSetAttribute(k3b_gemm, cudaFuncAttributeMaxDynamicSharedMemorySize, SMEM_BYTES);

    k_cvt<<<4096, 256>>>((const float4*)x, (float4*)pxt, Mn * Dn / 4);
    k_cvt_pair<<<512, 256>>>((const float4*)Wg, (const float4*)Wu, (float4*)pwb);
    k_cvt<<<512, 256>>>((const float4*)Wo, (float4*)pwo, Dn * SDn / 4);

    k1_gemm<<<dim3(2 * SDn / BN, Mn / BM), 256, SMEM_BYTES>>>();
    k2_tileprefix<<<(Bn * SDn) / 256, 256>>>();
    k3a_scan<<<Mn / TS, 512>>>();
    k3b_gemm<<<dim3(Dn / BN, Mn / BM), 256, SMEM_BYTES>>>(out);
}